// round 13
// baseline (speedup 1.0000x reference)
#include <cuda_runtime.h>
#include <cstdint>

#define TK_D        16384
#define TK_THREADS  256
#define TK_CHUNK    (TK_THREADS * 4)         // 1024 elements (fallback scans)
#define TK_NITER    (TK_D / TK_CHUNK)        // 16 (fallback scans)
#define TK_CAP      512
#define TK_NPOOL    3
#define TK_MAXROWS  8192
#define TK_SGRID    740                      // 148 SMs x 5 CTAs
#define CH_ELEMS    2048                     // 8 KB TMA chunk
#define CH_BYTES    (CH_ELEMS * 4)
#define CPR         (TK_D / CH_ELEMS)        // 8 chunks per row
#define NBUF        4                        // smem ring depth (32 KB)

// Compact winner exchange: (ordered_key << 32) | (D-1-idx), exactly k per row.
__device__ unsigned long long g_win[(size_t)TK_MAXROWS * TK_CAP];
__device__ int g_cnt[TK_MAXROWS];

struct TKShared {
    unsigned long long cand[TK_CAP];
    int cnt;
    int red;
};

// Order-preserving float->uint key: larger float <=> larger key.
__device__ __forceinline__ unsigned f2k(float f) {
    unsigned b = __float_as_uint(f);
    return b ^ ((unsigned)((int)b >> 31) | 0x80000000u);
}
__device__ __forceinline__ float k2f(unsigned u) {
    unsigned b = u ^ ((u & 0x80000000u) ? 0x80000000u : 0xFFFFFFFFu);
    return __uint_as_float(b);
}

__device__ __forceinline__ uint32_t smem_u32(const void* p) {
    uint32_t a;
    asm("{ .reg .u64 t; cvta.to.shared.u64 t, %1; cvt.u32.u64 %0, t; }"
        : "=r"(a) : "l"(p));
    return a;
}
__device__ __forceinline__ void tk_mbar_init(uint32_t mbar) {
    asm volatile("mbarrier.init.shared.b64 [%0], 1;" :: "r"(mbar) : "memory");
}
__device__ __forceinline__ void tk_mbar_expect(uint32_t mbar, uint32_t bytes) {
    asm volatile("mbarrier.arrive.expect_tx.shared.b64 _, [%0], %1;"
                 :: "r"(mbar), "r"(bytes) : "memory");
}
__device__ __forceinline__ void tk_bulk_g2s(uint32_t dst, const void* src,
                                            uint32_t bytes, uint32_t mbar) {
    asm volatile(
        "cp.async.bulk.shared::cta.global.mbarrier::complete_tx::bytes "
        "[%0], [%1], %2, [%3];"
        :: "r"(dst), "l"(src), "r"(bytes), "r"(mbar) : "memory");
}
__device__ __forceinline__ void tk_mbar_wait(uint32_t mbar, uint32_t parity) {
    asm volatile(
        "{\n\t.reg .pred P;\n\t"
        "W%=:\n\t"
        "mbarrier.try_wait.parity.acquire.cta.shared::cta.b64 P, [%0], %1, 0x989680;\n\t"
        "@P bra D%=;\n\t"
        "bra W%=;\n\t"
        "D%=:\n\t}"
        :: "r"(mbar), "r"(parity) : "memory");
}

__device__ __forceinline__ void tk_push(TKShared* sm, unsigned u, int idx) {
    int p = atomicAdd(&sm->cnt, 1);
    if (p < TK_CAP)
        sm->cand[p] = ((unsigned long long)u << 32) | (unsigned)(TK_D - 1 - idx);
}

// ===== Fallback helpers (global-memory scans; cold, never taken on N(0,1)) ==

__device__ void tk_scank(const float* __restrict__ rp,
                         unsigned klo, unsigned khi, TKShared* sm, int tid) {
    #pragma unroll 2
    for (int c = 0; c < TK_NITER; c++) {
        int base = c * TK_CHUNK + tid * 4;
        float4 v = *(const float4*)(rp + base);
        unsigned u0 = f2k(v.x), u1 = f2k(v.y), u2 = f2k(v.z), u3 = f2k(v.w);
        if (u0 > klo && u0 <= khi) tk_push(sm, u0, base + 0);
        if (u1 > klo && u1 <= khi) tk_push(sm, u1, base + 1);
        if (u2 > klo && u2 <= khi) tk_push(sm, u2, base + 2);
        if (u3 > klo && u3 <= khi) tk_push(sm, u3, base + 3);
    }
}

__device__ int tk_count(const float* __restrict__ rp, unsigned a, int b, int mode,
                        TKShared* sm, int tid) {
    __syncthreads();
    if (tid == 0) sm->red = 0;
    __syncthreads();
    int c = 0;
    #pragma unroll 2
    for (int ch = 0; ch < TK_NITER; ch++) {
        int base = ch * TK_CHUNK + tid * 4;
        float4 v = *(const float4*)(rp + base);
        unsigned u0 = f2k(v.x), u1 = f2k(v.y), u2 = f2k(v.z), u3 = f2k(v.w);
        if (mode == 0) {
            c += (int)(u0 > a) + (int)(u1 > a) + (int)(u2 > a) + (int)(u3 > a);
        } else {
            c += (int)(u0 == a && base + 0 <= b) + (int)(u1 == a && base + 1 <= b)
               + (int)(u2 == a && base + 2 <= b) + (int)(u3 == a && base + 3 <= b);
        }
    }
    #pragma unroll
    for (int o = 16; o > 0; o >>= 1) c += __shfl_xor_sync(0xffffffffu, c, o);
    if ((tid & 31) == 0) atomicAdd(&sm->red, c);
    __syncthreads();
    return sm->red;
}

// Exact selection: candidate i wins iff fewer than k candidates have a larger
// packed key. Keys unique (index embedded) -> exactly min(c,k) winners,
// emitted by rank into the compact buffer.
__device__ void tk_rank_emit(TKShared* sm, int c, int k, int row, int tid) {
    unsigned long long* wrow = g_win + (size_t)row * TK_CAP;
    for (int i = tid; i < c; i += TK_THREADS) {
        unsigned long long K = sm->cand[i];
        int r = 0;
        for (int j = 0; j < c; j++)
            r += (sm->cand[j] > K) ? 1 : 0;
        if (r < k) wrow[r] = K;
    }
}

// Cold fallback for one row. Block-uniform; ends with a barrier.
__device__ void tk_cold_row(const float* __restrict__ rp, TKShared* sm,
                            int cnt, int k, float tlo, int row, int tid) {
    unsigned lo_key = f2k(tlo);
    unsigned hi_key = 0xFFFFFFFFu;      // count(key > hi_key) == 0 < k

    {
        const unsigned krungs[6] = {f2k(1.2f), f2k(0.0f), f2k(-1.2f),
                                    f2k(-2.8f), f2k(-8.0f), 0u};
        int ki = 0;
        while (cnt < k && ki < 6) {
            unsigned k_new = krungs[ki];
            tk_scank(rp, k_new, lo_key, sm, tid);
            __syncthreads();
            cnt = sm->cnt;
            hi_key = lo_key;
            lo_key = k_new;
            ki++;
        }
    }

    if (cnt >= k && cnt <= TK_CAP) {
        tk_rank_emit(sm, cnt, k, row, tid);
        __syncthreads();
        return;
    }

    // Overflow: key-space bisection.
    unsigned lo = lo_key;
    while (hi_key - lo > 1u) {
        unsigned mid = lo + (hi_key - lo) / 2u;
        int cm = tk_count(rp, mid, 0, 0, sm, tid);
        if (cm < k) {
            hi_key = mid;
        } else if (cm <= TK_CAP) {
            __syncthreads();
            if (tid == 0) sm->cnt = 0;
            __syncthreads();
            tk_scank(rp, mid, 0xFFFFFFFFu, sm, tid);
            __syncthreads();
            tk_rank_emit(sm, sm->cnt, k, row, tid);
            __syncthreads();
            return;
        } else {
            lo = mid;
        }
    }

    // Massive-duplicate case: the k-th largest key is exactly hi_key.
    int cgt = tk_count(rp, hi_key, 0, 0, sm, tid);
    int needed = k - cgt;

    __syncthreads();
    if (tid == 0) sm->cnt = 0;
    __syncthreads();
    tk_scank(rp, hi_key, 0xFFFFFFFFu, sm, tid);
    __syncthreads();
    tk_rank_emit(sm, sm->cnt, k, row, tid);

    int ilo = -1, ihi = TK_D - 1;
    while (ihi - ilo > 1) {
        int im = (ilo + ihi) / 2;
        int ce = tk_count(rp, hi_key, im, 1, sm, tid);
        if (ce >= needed) ihi = im; else ilo = im;
    }
    __syncthreads();
    if (tid == 0) sm->red = cgt;
    __syncthreads();
    unsigned long long* wrow = g_win + (size_t)row * TK_CAP;
    #pragma unroll 2
    for (int ch = 0; ch < TK_NITER; ch++) {
        int base = ch * TK_CHUNK + tid * 4;
        float4 v = *(const float4*)(rp + base);
        #pragma unroll
        for (int e = 0; e < 4; e++) {
            float f = (e == 0) ? v.x : (e == 1) ? v.y : (e == 2) ? v.z : v.w;
            int idx = base + e;
            if (f2k(f) == hi_key && idx <= ihi) {
                int s = atomicAdd(&sm->red, 1);
                if (s < k)
                    wrow[s] = ((unsigned long long)hi_key << 32)
                            | (unsigned)(TK_D - 1 - idx);
            }
        }
    }
    __syncthreads();
}

// KERNEL A — TMA-pipelined pure READ stream. Persistent CTAs; 4-deep smem
// ring fed by cp.async.bulk (async engine does the latency hiding, no L1tex
// per-warp queueing); threads scan landed chunks from smem. 3-pool rotation
// (pool (r+1)%3 reset before row r's last-chunk barrier; last user was row
// r-2, complete before row r-1's barriers). Rank-emit overlaps next chunks.
__global__ __launch_bounds__(TK_THREADS, 5)
void tk_select_tma(const float* __restrict__ in,
                   const int* __restrict__ kptr, int nrows) {
    extern __shared__ float sbuf[];            // NBUF * CH_ELEMS floats (32 KB)
    __shared__ TKShared pool[TK_NPOOL];
    __shared__ unsigned long long mbar_st[NBUF];
    const int tid = threadIdx.x;
    const int bid = blockIdx.x;
    if (bid >= nrows) return;

    int k = kptr ? *kptr : 64;
    if (k < 1) k = 1;
    if (k > TK_CAP) k = TK_CAP;

    uint32_t mb0 = smem_u32(&mbar_st[0]);
    if (tid == 0) {
        pool[0].cnt = 0; pool[1].cnt = 0; pool[2].cnt = 0;
        #pragma unroll
        for (int b = 0; b < NBUF; b++) tk_mbar_init(mb0 + b * 8);
    }
    __syncthreads();

    const int nr = (nrows - bid + gridDim.x - 1) / gridDim.x;  // rows for CTA
    const int nchunks = nr * CPR;
    const uint32_t sb0 = smem_u32(sbuf);

    // Prologue: fill the ring.
    if (tid == 0) {
        #pragma unroll
        for (int b = 0; b < NBUF; b++) {
            if (b < nchunks) {
                int row = bid + (b / CPR) * gridDim.x;
                const float* src = in + (size_t)row * TK_D + (b % CPR) * CH_ELEMS;
                tk_mbar_expect(mb0 + b * 8, CH_BYTES);
                tk_bulk_g2s(sb0 + b * CH_BYTES, src, CH_BYTES, mb0 + b * 8);
            }
        }
    }

    const float TLO = 2.4f;
    int p = 0;

    for (int j = 0; j < nchunks; j++) {
        const int b = j & (NBUF - 1);
        const int cir = j & (CPR - 1);
        const int row = bid + (j / CPR) * gridDim.x;
        TKShared* sm = &pool[p];

        tk_mbar_wait(mb0 + b * 8, (j / NBUF) & 1);

        // Scan the landed chunk from smem (2 x LDS.128 per thread).
        const float4* cb = (const float4*)(sbuf + b * CH_ELEMS);
        const int base = cir * CH_ELEMS;
        #pragma unroll
        for (int i = 0; i < CH_ELEMS / (TK_THREADS * 4); i++) {
            float4 v = cb[i * TK_THREADS + tid];
            float m = fmaxf(fmaxf(v.x, v.y), fmaxf(v.z, v.w));
            if (m > TLO) {
                int eb = base + (i * TK_THREADS + tid) * 4;
                if (v.x > TLO) tk_push(sm, f2k(v.x), eb + 0);
                if (v.y > TLO) tk_push(sm, f2k(v.y), eb + 1);
                if (v.z > TLO) tk_push(sm, f2k(v.z), eb + 2);
                if (v.w > TLO) tk_push(sm, f2k(v.w), eb + 3);
            }
        }

        const bool rowend = (cir == CPR - 1);
        if (rowend && tid == 0) {
            int np = p + 1; if (np == TK_NPOOL) np = 0;
            pool[np].cnt = 0;                  // race-free (3-pool proof)
            g_cnt[row] = k;
        }
        __syncthreads();                       // scan done + reset published

        // Reissue this ring slot for chunk j+NBUF (keeps the pipe full even
        // across the rowend emit / cold path below).
        if (tid == 0) {
            int jn = j + NBUF;
            if (jn < nchunks) {
                int nrow = bid + (jn / CPR) * gridDim.x;
                const float* src =
                    in + (size_t)nrow * TK_D + (jn % CPR) * CH_ELEMS;
                tk_mbar_expect(mb0 + b * 8, CH_BYTES);
                tk_bulk_g2s(sb0 + b * CH_BYTES, src, CH_BYTES, mb0 + b * 8);
            }
        }

        if (rowend) {
            int cnt = sm->cnt;
            if (cnt >= k && cnt <= TK_CAP) {
                // Fast path: no trailing barrier — idle threads flow into the
                // next chunk's wait; pool p reused only at row+3.
                tk_rank_emit(sm, cnt, k, row, tid);
            } else {
                tk_cold_row(in + (size_t)row * TK_D, sm, cnt, k, TLO, row, tid);
            }
            p++; if (p == TK_NPOOL) p = 0;
        }
    }
}

// KERNEL B — pure WRITE stream (unchanged from R12; 81.8 us @ ~6.5 TB/s).
// One CTA per row, smem-staged single-touch output.
__global__ __launch_bounds__(TK_THREADS)
void tk_expand_kernel(float* __restrict__ out, int nrows) {
    extern __shared__ float srow[];            // TK_D floats = 64 KB
    const int tid = threadIdx.x;
    const int row = blockIdx.x;
    if (row >= nrows) return;

    int n = g_cnt[row];
    if (n > TK_CAP) n = TK_CAP;

    unsigned long long w0 = 0, w1 = 0;
    bool h0 = tid < n, h1 = tid + TK_THREADS < n;
    const unsigned long long* wrow = g_win + (size_t)row * TK_CAP;
    if (h0) w0 = wrow[tid];
    if (h1) w1 = wrow[tid + TK_THREADS];

    #pragma unroll
    for (int i = 0; i < TK_NITER; i++)
        *(float4*)(srow + (i * TK_THREADS + tid) * 4) =
            make_float4(0.f, 0.f, 0.f, 0.f);
    __syncthreads();

    if (h0) {
        int idx = TK_D - 1 - (int)(w0 & 0xFFFFFFFFu);
        srow[idx] = k2f((unsigned)(w0 >> 32));
    }
    if (h1) {
        int idx = TK_D - 1 - (int)(w1 & 0xFFFFFFFFu);
        srow[idx] = k2f((unsigned)(w1 >> 32));
    }
    __syncthreads();

    float* op = out + (size_t)row * TK_D;
    #pragma unroll
    for (int i = 0; i < TK_NITER; i++) {
        int q = (i * TK_THREADS + tid) * 4;
        __stcs((float4*)(op + q), *(const float4*)(srow + q));
    }
}

extern "C" void kernel_launch(void* const* d_in, const int* in_sizes, int n_in,
                              void* d_out, int out_size) {
    const float* in = (const float*)d_in[0];
    const int*   kp = (n_in > 1) ? (const int*)d_in[1] : nullptr;
    int N = in_sizes[0] / TK_D;          // 8192 rows
    if (N > TK_MAXROWS) N = TK_MAXROWS;
    (void)out_size;

    static bool init = false;
    if (!init) {
        cudaFuncSetAttribute(tk_expand_kernel,
                             cudaFuncAttributeMaxDynamicSharedMemorySize,
                             TK_D * (int)sizeof(float));
        init = true;
    }

    // Node 1: TMA-pipelined pure-read select -> compact winner buffer.
    int gsel = (N < TK_SGRID) ? N : TK_SGRID;
    tk_select_tma<<<gsel, TK_THREADS, NBUF * CH_BYTES>>>(in, kp, N);

    // Node 2: pure-write zero+scatter via smem staging (single-touch output).
    tk_expand_kernel<<<N, TK_THREADS, TK_D * sizeof(float)>>>((float*)d_out, N);
}